// round 8
// baseline (speedup 1.0000x reference)
#include <cuda_runtime.h>
#include <cuda_fp16.h>
#include <cstdint>

// Problem constants (match reference)
#define NN 100000
#define EE 6400000
#define DD 128
#define HH 15
#define HP 16   // padded hidden width (8 half2)

#define SCAN_B 1024
#define NBLK ((NN + SCAN_B - 1) / SCAN_B)   // 98

// ---------------- static scratch (no allocation allowed) ----------------
__device__ int     g_deg[NN];
__device__ float   g_dinv[NN];
__device__ int     g_ptr[NN + 1];
__device__ int     g_next[NN];
__device__ int     g_bsum[NBLK];
__device__ int     g_src[EE];                        // CSR by dst: source index only
__device__ __align__(128) __half2 g_h2[2][NN * 8];   // ping-pong PRE-SCALED tables (hs = dinv*h), fp16

// packed f32x2 add (sm_103a dual-FMA pipe; ptxas never emits this from C++)
__device__ __forceinline__ float2 addf32x2(float2 a, float2 b) {
    float2 r;
    asm("{\n\t"
        ".reg .b64 ra, rb, rc;\n\t"
        "mov.b64 ra, {%2, %3};\n\t"
        "mov.b64 rb, {%4, %5};\n\t"
        "add.rn.f32x2 rc, ra, rb;\n\t"
        "mov.b64 {%0, %1}, rc;\n\t"
        "}"
        : "=f"(r.x), "=f"(r.y)
        : "f"(a.x), "f"(a.y), "f"(b.x), "f"(b.y));
    return r;
}

// ---------------- build kernels ----------------
__global__ void zero_deg_kernel() {
    int i = blockIdx.x * blockDim.x + threadIdx.x;
    if (i < NN) g_deg[i] = 0;
}

__global__ void degree_kernel(const int* __restrict__ ei) {
    int e = (blockIdx.x * blockDim.x + threadIdx.x) * 4;
    if (e + 3 < EE) {
        int4 c4 = *reinterpret_cast<const int4*>(&ei[EE + e]);
        atomicAdd(&g_deg[c4.x], 1);
        atomicAdd(&g_deg[c4.y], 1);
        atomicAdd(&g_deg[c4.z], 1);
        atomicAdd(&g_deg[c4.w], 1);
    } else {
        for (int k = e; k < EE; k++) atomicAdd(&g_deg[ei[EE + k]], 1);
    }
}

__global__ void dinv_kernel() {
    int i = blockIdx.x * blockDim.x + threadIdx.x;
    if (i < NN) g_dinv[i] = rsqrtf((float)g_deg[i] + 1.0f);  // +1 = self loop
}

// -------- GEMM1: hs0 = dinv * (x @ W1), thread per (node, feature-pair), no shuffles --------
// Block: 256 threads = 32 nodes x 8 jpairs. NN % 32 == 0 -> grid exact.
#define XS_STRIDE 132   // 128 + 4 words pad: conflict-free 4-row float4 access
__global__ __launch_bounds__(256) void gemm1_kernel(const float* __restrict__ x,
                                                    const float* __restrict__ W1) {
    __shared__ float  xs[32 * XS_STRIDE];
    __shared__ float4 Wjx[8][33];   // Wjx[j][k4].q = W1[(4*k4+q)*15 + 2j]
    __shared__ float4 Wjy[8][33];   // Wjy[j][k4].q = W1[(4*k4+q)*15 + 2j+1] (0 for j==7)
    int t = threadIdx.x;

    // stage W (transposed into per-feature k-chunks)
    {
        int j = t >> 5, k4 = t & 31;   // 256 threads -> all (j,k4)
        float4 wx, wy;
        wx.x = W1[(4 * k4 + 0) * HH + 2 * j];
        wx.y = W1[(4 * k4 + 1) * HH + 2 * j];
        wx.z = W1[(4 * k4 + 2) * HH + 2 * j];
        wx.w = W1[(4 * k4 + 3) * HH + 2 * j];
        if (j < 7) {
            wy.x = W1[(4 * k4 + 0) * HH + 2 * j + 1];
            wy.y = W1[(4 * k4 + 1) * HH + 2 * j + 1];
            wy.z = W1[(4 * k4 + 2) * HH + 2 * j + 1];
            wy.w = W1[(4 * k4 + 3) * HH + 2 * j + 1];
        } else {
            wy = make_float4(0.f, 0.f, 0.f, 0.f);
        }
        Wjx[j][k4] = wx;
        Wjy[j][k4] = wy;
    }

    // stage x tile: 32 rows x 128 floats, coalesced float4 loads
    {
        const float4* xg = reinterpret_cast<const float4*>(x + (size_t)blockIdx.x * 32 * DD);
#pragma unroll
        for (int c = t; c < 32 * 32; c += 256) {
            int row = c >> 5, col4 = c & 31;
            float4 v = xg[row * 32 + col4];
            *reinterpret_cast<float4*>(&xs[row * XS_STRIDE + col4 * 4]) = v;
        }
    }
    __syncthreads();

    int r = t >> 3;        // node within tile
    int j = t & 7;         // feature pair
    const float4* xr = reinterpret_cast<const float4*>(&xs[r * XS_STRIDE]);

    float accx = 0.0f, accy = 0.0f;
#pragma unroll
    for (int k4 = 0; k4 < 32; k4++) {
        float4 xv = xr[k4];
        float4 wx = Wjx[j][k4];
        float4 wy = Wjy[j][k4];
        accx += xv.x * wx.x + xv.y * wx.y + xv.z * wx.z + xv.w * wx.w;
        accy += xv.x * wy.x + xv.y * wy.y + xv.z * wy.z + xv.w * wy.w;
    }

    int n = blockIdx.x * 32 + r;
    float dv = g_dinv[n];
    g_h2[0][n * 8 + j] = __floats2half2_rn(dv * accx, dv * accy);
}

// -------- 3-phase chip-wide exclusive scan of g_deg -> g_ptr/g_next --------
__global__ __launch_bounds__(SCAN_B) void block_sum_kernel() {
    __shared__ int s[32];
    int tid = threadIdx.x;
    int gid = blockIdx.x * SCAN_B + tid;
    int v = (gid < NN) ? g_deg[gid] : 0;
#pragma unroll
    for (int off = 16; off >= 1; off >>= 1) v += __shfl_xor_sync(0xffffffffu, v, off);
    if ((tid & 31) == 0) s[tid >> 5] = v;
    __syncthreads();
    if (tid < 32) {
        int w = s[tid];
#pragma unroll
        for (int off = 16; off >= 1; off >>= 1) w += __shfl_xor_sync(0xffffffffu, w, off);
        if (tid == 0) g_bsum[blockIdx.x] = w;
    }
}

__global__ void scan_bsum_kernel() {   // 1 block, 128 threads (NBLK=98 <= 128)
    __shared__ int s[128];
    int tid = threadIdx.x;
    int v = (tid < NBLK) ? g_bsum[tid] : 0;
    s[tid] = v;
    __syncthreads();
#pragma unroll
    for (int off = 1; off < 128; off <<= 1) {
        int t = (tid >= off) ? s[tid - off] : 0;
        __syncthreads();
        s[tid] += t;
        __syncthreads();
    }
    if (tid < NBLK) g_bsum[tid] = s[tid] - v;      // exclusive block offset
    if (tid == 127) g_ptr[NN] = s[127];            // total (= EE)
}

__global__ __launch_bounds__(SCAN_B) void scan_local_kernel() {
    __shared__ int s[SCAN_B];
    int tid = threadIdx.x;
    int gid = blockIdx.x * SCAN_B + tid;
    int v = (gid < NN) ? g_deg[gid] : 0;
    s[tid] = v;
    __syncthreads();
#pragma unroll
    for (int off = 1; off < SCAN_B; off <<= 1) {
        int t = (tid >= off) ? s[tid - off] : 0;
        __syncthreads();
        s[tid] += t;
        __syncthreads();
    }
    if (gid < NN) {
        int excl = g_bsum[blockIdx.x] + s[tid] - v;
        g_ptr[gid]  = excl;
        g_next[gid] = excl;
    }
}

__global__ void scatter_kernel(const int* __restrict__ ei) {
    int e = (blockIdx.x * blockDim.x + threadIdx.x) * 4;
    if (e + 3 < EE) {
        int4 r4 = *reinterpret_cast<const int4*>(&ei[e]);
        int4 c4 = *reinterpret_cast<const int4*>(&ei[EE + e]);
        g_src[atomicAdd(&g_next[c4.x], 1)] = r4.x;
        g_src[atomicAdd(&g_next[c4.y], 1)] = r4.y;
        g_src[atomicAdd(&g_next[c4.z], 1)] = r4.z;
        g_src[atomicAdd(&g_next[c4.w], 1)] = r4.w;
    } else {
        for (int k = e; k < EE; k++)
            g_src[atomicAdd(&g_next[ei[EE + k]], 1)] = ei[k];
    }
}

// ---------------- fused aggregation + epilogue GEMM ----------------
// hs tables pre-scaled by dinv. pre = dinv[n]*(sum_e hs[src_e] + hs[n]); z = relu(pre + b)
// MID: hs_out[n] = dinv[n]*(z @ W);   FINAL: out[n] = z @ Wc + bc
// 8 lanes per node (feature pair per lane), 4 nodes per warp.
// Edge loop software-pipelined: next chunk's index load issued before current gathers.

__global__ __launch_bounds__(256) void agg_mid_kernel(int src_buf,
                                                      const float* __restrict__ b,
                                                      const float* __restrict__ W) {
    __shared__ float2 Ws2[16 * 8];   // [k][jpair], padded row/col 15 -> 0
    int t = threadIdx.x;
    for (int i = t; i < 128; i += 256) {
        int k = i >> 3, j = i & 7;
        float wx = 0.0f, wy = 0.0f;
        if (k < HH) {
            wx = W[k * HH + 2 * j];
            if (2 * j + 1 < HH) wy = W[k * HH + 2 * j + 1];
        }
        Ws2[i] = make_float2(wx, wy);
    }
    __syncthreads();

    const __half2* __restrict__ hin = g_h2[src_buf];
    __half2* __restrict__ hout      = g_h2[1 - src_buf];

    int lane8 = t & 7;
    int warp  = t >> 5;
    int g     = (t >> 3) & 3;
    int n = blockIdx.x * 32 + warp * 4 + g;
    if (n >= NN) return;
    unsigned gmask = 0xFFu << (t & 24);

    int start = g_ptr[n], end = g_ptr[n + 1];
    float dv = g_dinv[n];
    float2 acc0 = __half22float2(__ldg(&hin[n * 8 + lane8]));   // self loop
    float2 acc1 = make_float2(0.0f, 0.0f);

    int e = start;
    int idx = (e + lane8 < end) ? __ldg(&g_src[e + lane8]) : 0;
    for (; e + 8 <= end; ) {
        int s0 = __shfl_sync(gmask, idx, 0, 8);
        int s1 = __shfl_sync(gmask, idx, 1, 8);
        int s2 = __shfl_sync(gmask, idx, 2, 8);
        int s3 = __shfl_sync(gmask, idx, 3, 8);
        int s4 = __shfl_sync(gmask, idx, 4, 8);
        int s5 = __shfl_sync(gmask, idx, 5, 8);
        int s6 = __shfl_sync(gmask, idx, 6, 8);
        int s7 = __shfl_sync(gmask, idx, 7, 8);
        e += 8;
        idx = (e + lane8 < end) ? __ldg(&g_src[e + lane8]) : 0;   // prefetch next chunk / tail
        float2 v0 = __half22float2(__ldg(&hin[s0 * 8 + lane8]));
        float2 v1 = __half22float2(__ldg(&hin[s1 * 8 + lane8]));
        float2 v2 = __half22float2(__ldg(&hin[s2 * 8 + lane8]));
        float2 v3 = __half22float2(__ldg(&hin[s3 * 8 + lane8]));
        float2 v4 = __half22float2(__ldg(&hin[s4 * 8 + lane8]));
        float2 v5 = __half22float2(__ldg(&hin[s5 * 8 + lane8]));
        float2 v6 = __half22float2(__ldg(&hin[s6 * 8 + lane8]));
        float2 v7 = __half22float2(__ldg(&hin[s7 * 8 + lane8]));
        acc0 = addf32x2(acc0, v0); acc1 = addf32x2(acc1, v1);
        acc0 = addf32x2(acc0, v2); acc1 = addf32x2(acc1, v3);
        acc0 = addf32x2(acc0, v4); acc1 = addf32x2(acc1, v5);
        acc0 = addf32x2(acc0, v6); acc1 = addf32x2(acc1, v7);
    }
    int rem = end - e;                       // tail (< 8), idx already loaded
    for (int j = 0; j < rem; j++) {
        int src = __shfl_sync(gmask, idx, j, 8);
        float2 v = __half22float2(__ldg(&hin[src * 8 + lane8]));
        acc0 = addf32x2(acc0, v);
    }
    float2 acc = addf32x2(acc0, acc1);

    float2 z;
    z.x = fmaxf(dv * acc.x + b[2 * lane8], 0.0f);
    z.y = fmaxf(dv * acc.y + ((2 * lane8 + 1 < HH) ? b[2 * lane8 + 1] : 0.0f), 0.0f);

    float2 ov = make_float2(0.0f, 0.0f);
#pragma unroll
    for (int k8 = 0; k8 < 8; k8++) {
        float zx = __shfl_sync(gmask, z.x, k8, 8);
        float zy = __shfl_sync(gmask, z.y, k8, 8);
        float2 w0 = Ws2[(2 * k8) * 8 + lane8];
        float2 w1 = Ws2[(2 * k8 + 1) * 8 + lane8];
        ov.x += zx * w0.x + zy * w1.x;
        ov.y += zx * w0.y + zy * w1.y;
    }
    hout[n * 8 + lane8] = __floats2half2_rn(dv * ov.x, dv * ov.y);
}

__global__ __launch_bounds__(256) void agg_final_kernel(int src_buf,
                                                        const float* __restrict__ b,
                                                        const float* __restrict__ Wc,
                                                        const float* __restrict__ bc,
                                                        float* __restrict__ out) {
    __shared__ float Wcs[16 * DD];   // padded row 15 -> 0
    __shared__ float bcs[DD];
    int t = threadIdx.x;
    for (int i = t; i < 16 * DD; i += 256) {
        int k = i >> 7;
        Wcs[i] = (k < HH) ? Wc[i] : 0.0f;
    }
    for (int i = t; i < DD; i += 256) bcs[i] = bc[i];
    __syncthreads();

    const __half2* __restrict__ hin = g_h2[src_buf];

    int lane8 = t & 7;
    int lane  = t & 31;
    int warp  = t >> 5;
    int g     = (t >> 3) & 3;
    int nbase = blockIdx.x * 32 + warp * 4;
    int n = nbase + g;
    if (n >= NN) return;
    unsigned gmask = 0xFFu << (t & 24);

    int start = g_ptr[n], end = g_ptr[n + 1];
    float dv = g_dinv[n];
    float2 acc0 = __half22float2(__ldg(&hin[n * 8 + lane8]));
    float2 acc1 = make_float2(0.0f, 0.0f);

    int e = start;
    int idx = (e + lane8 < end) ? __ldg(&g_src[e + lane8]) : 0;
    for (; e + 8 <= end; ) {
        int s0 = __shfl_sync(gmask, idx, 0, 8);
        int s1 = __shfl_sync(gmask, idx, 1, 8);
        int s2 = __shfl_sync(gmask, idx, 2, 8);
        int s3 = __shfl_sync(gmask, idx, 3, 8);
        int s4 = __shfl_sync(gmask, idx, 4, 8);
        int s5 = __shfl_sync(gmask, idx, 5, 8);
        int s6 = __shfl_sync(gmask, idx, 6, 8);
        int s7 = __shfl_sync(gmask, idx, 7, 8);
        e += 8;
        idx = (e + lane8 < end) ? __ldg(&g_src[e + lane8]) : 0;
        float2 v0 = __half22float2(__ldg(&hin[s0 * 8 + lane8]));
        float2 v1 = __half22float2(__ldg(&hin[s1 * 8 + lane8]));
        float2 v2 = __half22float2(__ldg(&hin[s2 * 8 + lane8]));
        float2 v3 = __half22float2(__ldg(&hin[s3 * 8 + lane8]));
        float2 v4 = __half22float2(__ldg(&hin[s4 * 8 + lane8]));
        float2 v5 = __half22float2(__ldg(&hin[s5 * 8 + lane8]));
        float2 v6 = __half22float2(__ldg(&hin[s6 * 8 + lane8]));
        float2 v7 = __half22float2(__ldg(&hin[s7 * 8 + lane8]));
        acc0 = addf32x2(acc0, v0); acc1 = addf32x2(acc1, v1);
        acc0 = addf32x2(acc0, v2); acc1 = addf32x2(acc1, v3);
        acc0 = addf32x2(acc0, v4); acc1 = addf32x2(acc1, v5);
        acc0 = addf32x2(acc0, v6); acc1 = addf32x2(acc1, v7);
    }
    int rem = end - e;
    for (int j = 0; j < rem; j++) {
        int src = __shfl_sync(gmask, idx, j, 8);
        float2 v = __half22float2(__ldg(&hin[src * 8 + lane8]));
        acc0 = addf32x2(acc0, v);
    }
    float2 acc = addf32x2(acc0, acc1);

    float2 z;
    z.x = fmaxf(dv * acc.x + b[2 * lane8], 0.0f);
    z.y = fmaxf(dv * acc.y + ((2 * lane8 + 1 < HH) ? b[2 * lane8 + 1] : 0.0f), 0.0f);

    // warp-cooperative epilogue: 4 nodes share each weight smem read.
    float res[4][4];
#pragma unroll
    for (int m = 0; m < 4; m++) {
        float bv = bcs[lane + 32 * m];
#pragma unroll
        for (int gg = 0; gg < 4; gg++) res[gg][m] = bv;
    }
#pragma unroll
    for (int k8 = 0; k8 < 8; k8++) {
        float w0[4], w1[4];
#pragma unroll
        for (int m = 0; m < 4; m++) {
            w0[m] = Wcs[(2 * k8) * DD + lane + 32 * m];
            w1[m] = Wcs[(2 * k8 + 1) * DD + lane + 32 * m];
        }
#pragma unroll
        for (int gg = 0; gg < 4; gg++) {
            float zx = __shfl_sync(0xffffffffu, z.x, gg * 8 + k8, 32);
            float zy = __shfl_sync(0xffffffffu, z.y, gg * 8 + k8, 32);
#pragma unroll
            for (int m = 0; m < 4; m++) res[gg][m] += zx * w0[m] + zy * w1[m];
        }
    }
#pragma unroll
    for (int gg = 0; gg < 4; gg++) {
        size_t base = (size_t)(nbase + gg) * DD + lane;
#pragma unroll
        for (int m = 0; m < 4; m++) out[base + 32 * m] = res[gg][m];
    }
}

// ---------------- launch ----------------
extern "C" void kernel_launch(void* const* d_in, const int* in_sizes, int n_in,
                              void* d_out, int out_size) {
    const float* x  = (const float*)d_in[0];
    const int*   ei = (const int*)d_in[1];
    const float* W1 = (const float*)d_in[2];
    const float* b1 = (const float*)d_in[3];
    const float* W2 = (const float*)d_in[4];
    const float* b2 = (const float*)d_in[5];
    const float* W3 = (const float*)d_in[6];
    const float* b3 = (const float*)d_in[7];
    const float* Wc = (const float*)d_in[8];
    const float* bc = (const float*)d_in[9];
    float* out = (float*)d_out;

    // ---- build CSR (by destination); gemm1 kept at launch index 3 (profiled slot) ----
    zero_deg_kernel<<<(NN + 255) / 256, 256>>>();
    degree_kernel<<<(EE / 4 + 255) / 256, 256>>>(ei);
    dinv_kernel<<<(NN + 255) / 256, 256>>>();
    gemm1_kernel<<<NN / 32, 256>>>(x, W1);               // needs only dinv; NN % 32 == 0
    block_sum_kernel<<<NBLK, SCAN_B>>>();
    scan_bsum_kernel<<<1, 128>>>();
    scan_local_kernel<<<NBLK, SCAN_B>>>();
    scatter_kernel<<<(EE / 4 + 255) / 256, 256>>>(ei);

    // ---- layer pipeline ----
    agg_mid_kernel<<<(NN + 31) / 32, 256>>>(0, b1, W2);
    agg_mid_kernel<<<(NN + 31) / 32, 256>>>(1, b2, W3);
    agg_final_kernel<<<(NN + 31) / 32, 256>>>(0, b3, Wc, bc, out);
}

// round 9
// speedup vs baseline: 1.3764x; 1.3764x over previous
#include <cuda_runtime.h>
#include <cuda_fp16.h>
#include <cstdint>

// Problem constants (match reference)
#define NN 100000
#define EE 6400000
#define DD 128
#define HH 15
#define HP 16   // padded hidden width (8 half2)

#define SCAN_B 1024
#define NBLK ((NN + SCAN_B - 1) / SCAN_B)   // 98

// ---------------- static scratch (no allocation allowed) ----------------
__device__ int     g_deg[NN];
__device__ float   g_dinv[NN];
__device__ int     g_ptr[NN + 1];
__device__ int     g_next[NN];
__device__ int     g_bsum[NBLK];
__device__ int     g_src[EE];                        // CSR by dst: source index only
__device__ __align__(128) __half2 g_h2[2][NN * 8];   // ping-pong PRE-SCALED tables (hs = dinv*h), fp16

// packed f32x2 add (sm_103a; ptxas never emits this from C++)
__device__ __forceinline__ float2 addf32x2(float2 a, float2 b) {
    float2 r;
    asm("{\n\t"
        ".reg .b64 ra, rb, rc;\n\t"
        "mov.b64 ra, {%2, %3};\n\t"
        "mov.b64 rb, {%4, %5};\n\t"
        "add.rn.f32x2 rc, ra, rb;\n\t"
        "mov.b64 {%0, %1}, rc;\n\t"
        "}"
        : "=f"(r.x), "=f"(r.y)
        : "f"(a.x), "f"(a.y), "f"(b.x), "f"(b.y));
    return r;
}

// packed f32x2 fma: c += a*b (elementwise pairs)
__device__ __forceinline__ float2 fmaf32x2(float ax, float ay, float bx, float by, float2 c) {
    float2 r;
    asm("{\n\t"
        ".reg .b64 ra, rb, rc;\n\t"
        "mov.b64 ra, {%2, %3};\n\t"
        "mov.b64 rb, {%4, %5};\n\t"
        "mov.b64 rc, {%6, %7};\n\t"
        "fma.rn.f32x2 rc, ra, rb, rc;\n\t"
        "mov.b64 {%0, %1}, rc;\n\t"
        "}"
        : "=f"(r.x), "=f"(r.y)
        : "f"(ax), "f"(ay), "f"(bx), "f"(by), "f"(c.x), "f"(c.y));
    return r;
}

// ---------------- build kernels ----------------
__global__ void zero_deg_kernel() {
    int i = blockIdx.x * blockDim.x + threadIdx.x;
    if (i < NN) g_deg[i] = 0;
}

__global__ void degree_kernel(const int* __restrict__ ei) {
    int e = (blockIdx.x * blockDim.x + threadIdx.x) * 4;
    if (e + 3 < EE) {
        int4 c4 = *reinterpret_cast<const int4*>(&ei[EE + e]);
        atomicAdd(&g_deg[c4.x], 1);
        atomicAdd(&g_deg[c4.y], 1);
        atomicAdd(&g_deg[c4.z], 1);
        atomicAdd(&g_deg[c4.w], 1);
    } else {
        for (int k = e; k < EE; k++) atomicAdd(&g_deg[ei[EE + k]], 1);
    }
}

__global__ void dinv_kernel() {
    int i = blockIdx.x * blockDim.x + threadIdx.x;
    if (i < NN) g_dinv[i] = rsqrtf((float)g_deg[i] + 1.0f);  // +1 = self loop
}

// -------- GEMM1: hs0 = dinv * (x @ W1) --------
// 64-node tile, 256 threads = 32 row-groups x 8 jpairs, 2 rows/thread.
// W fetch amortized over 2 rows; k-packed fma.rn.f32x2 halves FFMA instr count.
#define G1_ROWS 64
#define XS_STRIDE 132   // 128 + 4 words pad: conflict-free row access
__global__ __launch_bounds__(256) void gemm1_kernel(const float* __restrict__ x,
                                                    const float* __restrict__ W1) {
    __shared__ float  xs[G1_ROWS * XS_STRIDE];  // 33.8 KB
    __shared__ float4 Wjx[8][33];   // Wjx[j][k4].q = W1[(4*k4+q)*15 + 2j]
    __shared__ float4 Wjy[8][33];   // Wjy[j][k4].q = W1[(4*k4+q)*15 + 2j+1] (0 for j==7)
    int t = threadIdx.x;
    int nbase = blockIdx.x * G1_ROWS;
    int nrows = NN - nbase; if (nrows > G1_ROWS) nrows = G1_ROWS;

    // stage W (transposed into per-feature k-chunks)
    {
        int j = t >> 5, k4 = t & 31;   // 256 threads cover all (j,k4)
        float4 wx, wy;
        wx.x = W1[(4 * k4 + 0) * HH + 2 * j];
        wx.y = W1[(4 * k4 + 1) * HH + 2 * j];
        wx.z = W1[(4 * k4 + 2) * HH + 2 * j];
        wx.w = W1[(4 * k4 + 3) * HH + 2 * j];
        if (j < 7) {
            wy.x = W1[(4 * k4 + 0) * HH + 2 * j + 1];
            wy.y = W1[(4 * k4 + 1) * HH + 2 * j + 1];
            wy.z = W1[(4 * k4 + 2) * HH + 2 * j + 1];
            wy.w = W1[(4 * k4 + 3) * HH + 2 * j + 1];
        } else {
            wy = make_float4(0.f, 0.f, 0.f, 0.f);
        }
        Wjx[j][k4] = wx;
        Wjy[j][k4] = wy;
    }

    // stage x tile (guarded for the 32-row last block), coalesced float4
    {
        const float4* xg = reinterpret_cast<const float4*>(x + (size_t)nbase * DD);
        for (int c = t; c < nrows * 32; c += 256) {
            int row = c >> 5, col4 = c & 31;
            *reinterpret_cast<float4*>(&xs[row * XS_STRIDE + col4 * 4]) = xg[row * 32 + col4];
        }
    }
    __syncthreads();

    int j  = t & 7;        // feature pair
    int rg = t >> 3;       // row group 0..31; rows rg and rg+32
    const float4* xr0 = reinterpret_cast<const float4*>(&xs[rg * XS_STRIDE]);
    const float4* xr1 = reinterpret_cast<const float4*>(&xs[(rg + 32) * XS_STRIDE]);

    float2 ax0 = make_float2(0.f, 0.f), ay0 = ax0, ax1 = ax0, ay1 = ax0;  // k-packed partials
#pragma unroll
    for (int k4 = 0; k4 < 32; k4++) {
        float4 wx = Wjx[j][k4];
        float4 wy = Wjy[j][k4];
        float4 v0 = xr0[k4];
        float4 v1 = xr1[k4];
        ax0 = fmaf32x2(v0.x, v0.y, wx.x, wx.y, ax0);
        ax0 = fmaf32x2(v0.z, v0.w, wx.z, wx.w, ax0);
        ay0 = fmaf32x2(v0.x, v0.y, wy.x, wy.y, ay0);
        ay0 = fmaf32x2(v0.z, v0.w, wy.z, wy.w, ay0);
        ax1 = fmaf32x2(v1.x, v1.y, wx.x, wx.y, ax1);
        ax1 = fmaf32x2(v1.z, v1.w, wx.z, wx.w, ax1);
        ay1 = fmaf32x2(v1.x, v1.y, wy.x, wy.y, ay1);
        ay1 = fmaf32x2(v1.z, v1.w, wy.z, wy.w, ay1);
    }

    int n0 = nbase + rg;
    float dv0 = g_dinv[n0];
    g_h2[0][n0 * 8 + j] = __floats2half2_rn(dv0 * (ax0.x + ax0.y), dv0 * (ay0.x + ay0.y));
    if (rg + 32 < nrows) {
        int n1 = n0 + 32;
        float dv1 = g_dinv[n1];
        g_h2[0][n1 * 8 + j] = __floats2half2_rn(dv1 * (ax1.x + ax1.y), dv1 * (ay1.x + ay1.y));
    }
}

// -------- 3-phase chip-wide exclusive scan of g_deg -> g_ptr/g_next --------
__global__ __launch_bounds__(SCAN_B) void block_sum_kernel() {
    __shared__ int s[32];
    int tid = threadIdx.x;
    int gid = blockIdx.x * SCAN_B + tid;
    int v = (gid < NN) ? g_deg[gid] : 0;
#pragma unroll
    for (int off = 16; off >= 1; off >>= 1) v += __shfl_xor_sync(0xffffffffu, v, off);
    if ((tid & 31) == 0) s[tid >> 5] = v;
    __syncthreads();
    if (tid < 32) {
        int w = s[tid];
#pragma unroll
        for (int off = 16; off >= 1; off >>= 1) w += __shfl_xor_sync(0xffffffffu, w, off);
        if (tid == 0) g_bsum[blockIdx.x] = w;
    }
}

__global__ void scan_bsum_kernel() {   // 1 block, 128 threads (NBLK=98 <= 128)
    __shared__ int s[128];
    int tid = threadIdx.x;
    int v = (tid < NBLK) ? g_bsum[tid] : 0;
    s[tid] = v;
    __syncthreads();
#pragma unroll
    for (int off = 1; off < 128; off <<= 1) {
        int t = (tid >= off) ? s[tid - off] : 0;
        __syncthreads();
        s[tid] += t;
        __syncthreads();
    }
    if (tid < NBLK) g_bsum[tid] = s[tid] - v;      // exclusive block offset
    if (tid == 127) g_ptr[NN] = s[127];            // total (= EE)
}

__global__ __launch_bounds__(SCAN_B) void scan_local_kernel() {
    __shared__ int s[SCAN_B];
    int tid = threadIdx.x;
    int gid = blockIdx.x * SCAN_B + tid;
    int v = (gid < NN) ? g_deg[gid] : 0;
    s[tid] = v;
    __syncthreads();
#pragma unroll
    for (int off = 1; off < SCAN_B; off <<= 1) {
        int t = (tid >= off) ? s[tid - off] : 0;
        __syncthreads();
        s[tid] += t;
        __syncthreads();
    }
    if (gid < NN) {
        int excl = g_bsum[blockIdx.x] + s[tid] - v;
        g_ptr[gid]  = excl;
        g_next[gid] = excl;
    }
}

__global__ void scatter_kernel(const int* __restrict__ ei) {
    int e = (blockIdx.x * blockDim.x + threadIdx.x) * 4;
    if (e + 3 < EE) {
        int4 r4 = *reinterpret_cast<const int4*>(&ei[e]);
        int4 c4 = *reinterpret_cast<const int4*>(&ei[EE + e]);
        g_src[atomicAdd(&g_next[c4.x], 1)] = r4.x;
        g_src[atomicAdd(&g_next[c4.y], 1)] = r4.y;
        g_src[atomicAdd(&g_next[c4.z], 1)] = r4.z;
        g_src[atomicAdd(&g_next[c4.w], 1)] = r4.w;
    } else {
        for (int k = e; k < EE; k++)
            g_src[atomicAdd(&g_next[ei[EE + k]], 1)] = ei[k];
    }
}

// ---------------- fused aggregation + epilogue GEMM (exact 323us-proven form) ----------------
// hs tables pre-scaled by dinv. pre = dinv[n]*(sum_e hs[src_e] + hs[n]); z = relu(pre + b)
// MID: hs_out[n] = dinv[n]*(z @ W);   FINAL: out[n] = z @ Wc + bc
// 8 lanes per node (feature pair per lane), 4 nodes per warp.

__global__ __launch_bounds__(256) void agg_mid_kernel(int src_buf,
                                                      const float* __restrict__ b,
                                                      const float* __restrict__ W) {
    __shared__ float2 Ws2[16 * 8];   // [k][jpair], padded row/col 15 -> 0
    int t = threadIdx.x;
    for (int i = t; i < 128; i += 256) {
        int k = i >> 3, j = i & 7;
        float wx = 0.0f, wy = 0.0f;
        if (k < HH) {
            wx = W[k * HH + 2 * j];
            if (2 * j + 1 < HH) wy = W[k * HH + 2 * j + 1];
        }
        Ws2[i] = make_float2(wx, wy);
    }
    __syncthreads();

    const __half2* __restrict__ hin = g_h2[src_buf];
    __half2* __restrict__ hout      = g_h2[1 - src_buf];

    int lane8 = t & 7;
    int warp  = t >> 5;
    int g     = (t >> 3) & 3;
    int n = blockIdx.x * 32 + warp * 4 + g;
    if (n >= NN) return;
    unsigned gmask = 0xFFu << (t & 24);

    int start = g_ptr[n], end = g_ptr[n + 1];
    float dv = g_dinv[n];
    float2 acc = __half22float2(__ldg(&hin[n * 8 + lane8]));   // self loop

    int e = start;
    for (; e + 8 <= end; e += 8) {          // unguarded full chunks -> batched gathers
        int idx = __ldg(&g_src[e + lane8]);
        int s[8];
#pragma unroll
        for (int j = 0; j < 8; j++) s[j] = __shfl_sync(gmask, idx, j, 8);
#pragma unroll
        for (int j = 0; j < 8; j++) {
            float2 v = __half22float2(__ldg(&hin[s[j] * 8 + lane8]));
            acc = addf32x2(acc, v);
        }
    }
    int rem = end - e;                       // tail (< 8)
    if (rem > 0) {
        int idx = (lane8 < rem) ? __ldg(&g_src[e + lane8]) : 0;
        for (int j = 0; j < rem; j++) {
            int src = __shfl_sync(gmask, idx, j, 8);
            float2 v = __half22float2(__ldg(&hin[src * 8 + lane8]));
            acc = addf32x2(acc, v);
        }
    }

    float2 z;
    z.x = fmaxf(dv * acc.x + b[2 * lane8], 0.0f);
    z.y = fmaxf(dv * acc.y + ((2 * lane8 + 1 < HH) ? b[2 * lane8 + 1] : 0.0f), 0.0f);

    float2 ov = make_float2(0.0f, 0.0f);
#pragma unroll
    for (int k8 = 0; k8 < 8; k8++) {
        float zx = __shfl_sync(gmask, z.x, k8, 8);
        float zy = __shfl_sync(gmask, z.y, k8, 8);
        float2 w0 = Ws2[(2 * k8) * 8 + lane8];
        float2 w1 = Ws2[(2 * k8 + 1) * 8 + lane8];
        ov.x += zx * w0.x + zy * w1.x;
        ov.y += zx * w0.y + zy * w1.y;
    }
    hout[n * 8 + lane8] = __floats2half2_rn(dv * ov.x, dv * ov.y);
}

__global__ __launch_bounds__(256) void agg_final_kernel(int src_buf,
                                                        const float* __restrict__ b,
                                                        const float* __restrict__ Wc,
                                                        const float* __restrict__ bc,
                                                        float* __restrict__ out) {
    __shared__ float Wcs[16 * DD];   // padded row 15 -> 0
    __shared__ float bcs[DD];
    int t = threadIdx.x;
    for (int i = t; i < 16 * DD; i += 256) {
        int k = i >> 7;
        Wcs[i] = (k < HH) ? Wc[i] : 0.0f;
    }
    for (int i = t; i < DD; i += 256) bcs[i] = bc[i];
    __syncthreads();

    const __half2* __restrict__ hin = g_h2[src_buf];

    int lane8 = t & 7;
    int lane  = t & 31;
    int warp  = t >> 5;
    int g     = (t >> 3) & 3;
    int nbase = blockIdx.x * 32 + warp * 4;
    int n = nbase + g;
    if (n >= NN) return;
    unsigned gmask = 0xFFu << (t & 24);

    int start = g_ptr[n], end = g_ptr[n + 1];
    float dv = g_dinv[n];
    float2 acc = __half22float2(__ldg(&hin[n * 8 + lane8]));

    int e = start;
    for (; e + 8 <= end; e += 8) {
        int idx = __ldg(&g_src[e + lane8]);
        int s[8];
#pragma unroll
        for (int j = 0; j < 8; j++) s[j] = __shfl_sync(gmask, idx, j, 8);
#pragma unroll
        for (int j = 0; j < 8; j++) {
            float2 v = __half22float2(__ldg(&hin[s[j] * 8 + lane8]));
            acc = addf32x2(acc, v);
        }
    }
    int rem = end - e;
    if (rem > 0) {
        int idx = (lane8 < rem) ? __ldg(&g_src[e + lane8]) : 0;
        for (int j = 0; j < rem; j++) {
            int src = __shfl_sync(gmask, idx, j, 8);
            float2 v = __half22float2(__ldg(&hin[src * 8 + lane8]));
            acc = addf32x2(acc, v);
        }
    }

    float2 z;
    z.x = fmaxf(dv * acc.x + b[2 * lane8], 0.0f);
    z.y = fmaxf(dv * acc.y + ((2 * lane8 + 1 < HH) ? b[2 * lane8 + 1] : 0.0f), 0.0f);

    // warp-cooperative epilogue: 4 nodes share each weight smem read.
    float res[4][4];
#pragma unroll
    for (int m = 0; m < 4; m++) {
        float bv = bcs[lane + 32 * m];
#pragma unroll
        for (int gg = 0; gg < 4; gg++) res[gg][m] = bv;
    }
#pragma unroll
    for (int k8 = 0; k8 < 8; k8++) {
        float w0[4], w1[4];
#pragma unroll
        for (int m = 0; m < 4; m++) {
            w0[m] = Wcs[(2 * k8) * DD + lane + 32 * m];
            w1[m] = Wcs[(2 * k8 + 1) * DD + lane + 32 * m];
        }
#pragma unroll
        for (int gg = 0; gg < 4; gg++) {
            float zx = __shfl_sync(0xffffffffu, z.x, gg * 8 + k8, 32);
            float zy = __shfl_sync(0xffffffffu, z.y, gg * 8 + k8, 32);
#pragma unroll
            for (int m = 0; m < 4; m++) res[gg][m] += zx * w0[m] + zy * w1[m];
        }
    }
#pragma unroll
    for (int gg = 0; gg < 4; gg++) {
        size_t base = (size_t)(nbase + gg) * DD + lane;
#pragma unroll
        for (int m = 0; m < 4; m++) out[base + 32 * m] = res[gg][m];
    }
}

// ---------------- launch ----------------
extern "C" void kernel_launch(void* const* d_in, const int* in_sizes, int n_in,
                              void* d_out, int out_size) {
    const float* x  = (const float*)d_in[0];
    const int*   ei = (const int*)d_in[1];
    const float* W1 = (const float*)d_in[2];
    const float* b1 = (const float*)d_in[3];
    const float* W2 = (const float*)d_in[4];
    const float* b2 = (const float*)d_in[5];
    const float* W3 = (const float*)d_in[6];
    const float* b3 = (const float*)d_in[7];
    const float* Wc = (const float*)d_in[8];
    const float* bc = (const float*)d_in[9];
    float* out = (float*)d_out;

    // ---- build CSR (by destination); gemm1 kept at launch index 3 (profiled slot) ----
    zero_deg_kernel<<<(NN + 255) / 256, 256>>>();
    degree_kernel<<<(EE / 4 + 255) / 256, 256>>>(ei);
    dinv_kernel<<<(NN + 255) / 256, 256>>>();
    gemm1_kernel<<<(NN + G1_ROWS - 1) / G1_ROWS, 256>>>(x, W1);   // needs only dinv
    block_sum_kernel<<<NBLK, SCAN_B>>>();
    scan_bsum_kernel<<<1, 128>>>();
    scan_local_kernel<<<NBLK, SCAN_B>>>();
    scatter_kernel<<<(EE / 4 + 255) / 256, 256>>>(ei);

    // ---- layer pipeline ----
    agg_mid_kernel<<<(NN + 31) / 32, 256>>>(0, b1, W2);
    agg_mid_kernel<<<(NN + 31) / 32, 256>>>(1, b2, W3);
    agg_final_kernel<<<(NN + 31) / 32, 256>>>(0, b3, Wc, bc, out);
}